// round 11
// baseline (speedup 1.0000x reference)
#include <cuda_runtime.h>
#include <cstdint>

// ---------------------------------------------------------------------------
// EmbeddingLoss, single persistent kernel, fine-grained dataflow sync.
//   P1: prep  (seg u8, per-block counts, bce partials)      -> flags region/b/all
//   P2: bins  (segmented sum/sumsq, smem bins, dual ring)   -> flags be
//   P3: partial reductions (blocks 0..68)                   -> flags done
//   P4: block 0 finalize -> scalar, then resets counters
// All inter-block sync via integer atomics; FP reductions fixed-order ->
// bit-deterministic. Grid fully resident (occupancy-checked fallback).
// ---------------------------------------------------------------------------

constexpr int B_   = 4;
constexpr int E_   = 16;
constexpr int N_   = 96 * 96 * 96;   // 884736 voxels per batch
constexpr int N4_  = N_ / 4;         // 221184 float4 groups per batch
constexpr int KC   = 32;
constexpr int T_   = 96;             // threads per block (3 warps)

constexpr int CHA_MAX = 18;

__device__ unsigned char g_seg[(long)B_ * N_];        // 3.5 MB
__device__ float2        g_pSum[64 * CHA_MAX * KC];   // [be][ch][k]
__device__ float         g_pCnt[1152 * KC];           // [prep-block][k]
__device__ float         g_pBce[1152];
__device__ float2        g_sSum[64 * KC];
__device__ float         g_sCnt[B_ * KC];
__device__ float         g_sBce;

// dataflow counters (zero at load; block 0 re-zeros at end of every launch)
__device__ int g_rgn[B_ * CHA_MAX];   // seg regions ready (target RPB)
__device__ int g_beC[64];             // P2 units done per be (target CHA)
__device__ int g_bC[B_];              // P1 blocks done per batch (target PB)
__device__ int g_p1C;                 // all P1 (target GRIDN)
__device__ int g_doneC;               // P3 units done (target 69)

__device__ __forceinline__ void wait_ge(int* c, int target)
{
    if (threadIdx.x == 0) {
        while (*(volatile int*)c < target) __nanosleep(64);
        __threadfence();
    }
    __syncthreads();
}

template<int GRIDN>
__global__ __launch_bounds__(T_, 8) void k_all(const float* __restrict__ emb,
                                               const float* __restrict__ masks,
                                               const int*   __restrict__ lbl,
                                               const float* __restrict__ tmask,
                                               float*       __restrict__ out)
{
    constexpr int PB  = GRIDN / B_;          // P1 blocks per batch
    constexpr int PV  = (B_ * N4_) / GRIDN;  // float4 per P1 slice
    constexpr int PIT = PV / T_;
    constexpr int CHA = GRIDN / 64;          // bins chunks per (b,e)
    constexpr int C4A = N4_ / CHA;
    constexpr int BIT = C4A / T_;
    constexpr int RPB = C4A / PV;            // P1 blocks per seg region
    static_assert(PIT * T_ == PV && CHA * 64 == GRIDN && C4A * CHA == N4_
                  && BIT * T_ == C4A && RPB * PV == C4A && PB * PV == N4_
                  && (BIT % 8) == 0 && CHA <= CHA_MAX, "partition");

    __shared__ __align__(16) unsigned char sraw[25600];   // unioned per phase

    const int tid  = threadIdx.x;
    const int bid  = blockIdx.x;
    const int lane = tid & 31;
    const int w    = tid >> 5;     // 0..2

    // ======================= P1: prep =======================
    {
        unsigned char* cnt8 = sraw;                       // 96*33 = 3168 B
        float* redC = (float*)(sraw + 3168);              // 3*32 floats
        float* redB = (float*)(sraw + 3168 + 3 * 32 * 4); // 3 floats

        unsigned char* mybin = cnt8 + tid * 33;
#pragma unroll
        for (int k = 0; k < KC; k++) mybin[k] = 0;

        const long base4 = (long)bid * PV;
        const int4*   lv = (const int4*)lbl     + base4;
        const float4* tv = (const float4*)tmask + base4;
        const float4* xv = (const float4*)masks + base4;
        uchar4*       sv = (uchar4*)g_seg + base4;

        float bce = 0.f;
#pragma unroll
        for (int it = 0; it < PIT; it++) {
            const int i = tid + it * T_;
            int4   L  = __ldcs(&lv[i]);
            float4 Tt = __ldcs(&tv[i]);
            float4 X  = __ldcs(&xv[i]);
            uchar4 s;
#define PREP1(comp)                                                            \
            {                                                                  \
                bool m = (Tt.comp != 0.f) && ((unsigned)L.comp < 32u);         \
                s.comp = m ? (unsigned char)L.comp : (unsigned char)255;       \
                if (m) mybin[L.comp] = mybin[L.comp] + 1;                      \
                float a = fabsf(X.comp);                                       \
                bce += fmaxf(X.comp, 0.f) - X.comp * Tt.comp                   \
                     + __logf(1.f + __expf(-a));                               \
            }
            PREP1(x) PREP1(y) PREP1(z) PREP1(w)
#undef PREP1
            sv[i] = s;
        }
        __syncthreads();

        float acc = 0.f;
#pragma unroll 8
        for (int t = 0; t < 32; t++) acc += (float)cnt8[(w * 32 + t) * 33 + lane];
        redC[w * 32 + lane] = acc;

        float bb = bce;
#pragma unroll
        for (int o = 16; o; o >>= 1) bb += __shfl_xor_sync(0xffffffffu, bb, o);
        if (lane == 0) redB[w] = bb;
        __syncthreads();

        if (w == 0) {
            float tot = redC[lane] + redC[32 + lane] + redC[64 + lane];
            g_pCnt[bid * KC + lane] = tot;
            if (lane == 0) g_pBce[bid] = redB[0] + redB[1] + redB[2];
        }
        __syncthreads();                        // all P1 writes complete
        if (tid == 0) {
            __threadfence();
            const int b1 = bid / PB;
            const int r1 = bid - b1 * PB;
            atomicAdd(&g_rgn[b1 * CHA_MAX + r1 / RPB], 1);
            atomicAdd(&g_bC[b1], 1);
            atomicAdd(&g_p1C, 1);
        }
    }

    // ======================= P2: bins =======================
    {
        float2* bins = (float2*)sraw;   // 32*96 float2 = 24576 B
        const int be  = bid & 63;       // b*16 + e
        const int chv = bid >> 6;       // 0..CHA-1
        const int b   = be >> 4;

#pragma unroll
        for (int k = 0; k < KC; k++) bins[k * T_ + tid] = make_float2(0.f, 0.f);

        const float4* evp = (const float4*)emb   + (long)be * N4_ + (long)chv * C4A + tid;
        const uchar4* svp = (const uchar4*)g_seg + (long)b  * N4_ + (long)chv * C4A + tid;

        // emb does not depend on seg: start its ring before the region wait
        float4 vb[4];
#pragma unroll
        for (int p = 0; p < 4; p++) vb[p] = __ldcs(&evp[p * T_]);

        wait_ge(&g_rgn[b * CHA_MAX + chv], RPB);   // seg region ready

        uchar4 sb[8];                               // deep seg ring (L2 lat)
#pragma unroll
        for (int p = 0; p < 8; p++) sb[p] = svp[p * T_];

#pragma unroll 8
        for (int it = 0; it < BIT; it++) {
            float4 v = vb[it & 3];
            uchar4 s = sb[it & 7];
            if (it + 4 < BIT) vb[it & 3] = __ldcs(&evp[(it + 4) * T_]);
            if (it + 8 < BIT) sb[it & 7] = svp[(it + 8) * T_];
#define ACC1(sc, vc)                                                   \
            if (s.sc != 255) {                                         \
                float2 a = bins[(int)s.sc * T_ + tid];                 \
                a.x += v.vc; a.y += v.vc * v.vc;                       \
                bins[(int)s.sc * T_ + tid] = a;                        \
            }
            ACC1(x, x) ACC1(y, y) ACC1(z, z) ACC1(w, w)
#undef ACC1
        }
        __syncthreads();

        // warp w sums row k=lane over its 32-column window, +lane swizzled
        float2 acc = make_float2(0.f, 0.f);
#pragma unroll 8
        for (int t = 0; t < 32; t++) {
            int col = w * 32 + t + lane;
            if (col >= T_) col -= T_;
            float2 x = bins[lane * T_ + col];
            acc.x += x.x; acc.y += x.y;
        }
        __syncthreads();               // reads done -> reuse bins row 0
        bins[w * 32 + lane] = acc;
        __syncthreads();

        if (w == 0) {
            float2 t0 = bins[lane], t1 = bins[32 + lane], t2 = bins[64 + lane];
            float2 tot = make_float2(t0.x + t1.x + t2.x, t0.y + t1.y + t2.y);
            g_pSum[(be * CHA + chv) * KC + lane] = tot;
        }
        __syncthreads();
        if (tid == 0) {
            __threadfence();
            atomicAdd(&g_beC[be], 1);
        }
    }

    // ======================= P3: partial reductions =======================
    if (bid < 69) {
        float2* red2 = (float2*)sraw;
        float*  redf = (float*)sraw;
        if (bid < 64) {
            wait_ge(&g_beC[bid], CHA);
            float2 acc = make_float2(0.f, 0.f);
            for (int c = w; c < CHA; c += 3) {
                float2 x = g_pSum[(bid * CHA + c) * KC + lane];
                acc.x += x.x; acc.y += x.y;
            }
            red2[w * 32 + lane] = acc;
            __syncthreads();
            if (w == 0) {
                float2 a0 = red2[lane], a1 = red2[32 + lane], a2 = red2[64 + lane];
                g_sSum[bid * KC + lane] =
                    make_float2(a0.x + a1.x + a2.x, a0.y + a1.y + a2.y);
            }
        } else if (bid < 68) {
            const int b2 = bid - 64;
            wait_ge(&g_bC[b2], PB);
            float c = 0.f;
            for (int c0 = w; c0 < PB; c0 += 3)
                c += g_pCnt[(b2 * PB + c0) * KC + lane];
            redf[w * 32 + lane] = c;
            __syncthreads();
            if (w == 0)
                g_sCnt[b2 * KC + lane] = redf[lane] + redf[32 + lane] + redf[64 + lane];
        } else {
            wait_ge(&g_p1C, GRIDN);
            float a = 0.f;
            for (int q = tid; q < GRIDN; q += T_) a += g_pBce[q];
#pragma unroll
            for (int o = 16; o; o >>= 1) a += __shfl_xor_sync(0xffffffffu, a, o);
            if (lane == 0) redf[w] = a;
            __syncthreads();
            if (tid == 0) g_sBce = redf[0] + redf[1] + redf[2];
        }
        __syncthreads();
        if (tid == 0) {
            __threadfence();
            atomicAdd(&g_doneC, 1);
        }
    }

    // ======================= P4: finalize (block 0) =======================
    if (bid == 0) {
        wait_ge(&g_doneC, 69);

        float (*sCent)[KC][E_ + 1] = (float (*)[KC][E_ + 1])sraw;   // 8704 B
        float* sRes = (float*)(sraw + B_ * KC * (E_ + 1) * 4);      // 12 floats

        for (int bb = w; bb < B_; bb += 3) {       // w0: b=0,3  w1: b=1  w2: b=2
            float cnt  = g_sCnt[bb * KC + lane];
            float safe = fmaxf(cnt, 1.f);
            float center[E_];
            float sq = 0.f, cs = 0.f;
#pragma unroll
            for (int e = 0; e < E_; e++) {
                float2 s = g_sSum[(bb * E_ + e) * KC + lane];
                float c = s.x / safe;
                center[e] = c;
                cs += c * c;
                sq += s.y;
                sCent[bb][lane][e] = c;
            }
            bool fg = (cnt > 0.f) && (lane > 0);
            unsigned fgm = __ballot_sync(0xffffffffu, fg);
            float C = (float)__popc(fgm);
            __syncwarp();

            float vi = fg ? (sq / safe - cs) : 0.f;
            float vr = fg ? sqrtf(cs) : 0.f;
            float hs = 0.f;
            for (int j = 0; j < KC; j++) {
                if ((fgm >> j) & 1u) {
                    float d2 = 0.f;
#pragma unroll
                    for (int e = 0; e < E_; e++) {
                        float d = center[e] - sCent[bb][j][e];
                        d2 += d * d;
                    }
                    if (fg && j != lane) {
                        float d = sqrtf(d2);
                        float h = fmaxf(2.f * 1.5f - d, 0.f);
                        hs += h * h;
                    }
                }
            }
#pragma unroll
            for (int o = 16; o; o >>= 1) {
                vi += __shfl_xor_sync(0xffffffffu, vi, o);
                vr += __shfl_xor_sync(0xffffffffu, vr, o);
                hs += __shfl_xor_sync(0xffffffffu, hs, o);
            }
            if (lane == 0) {
                float Cs = fmaxf(C, 1.f);
                sRes[bb * 3 + 0] = (C >= 1.f) ? vi / Cs : 0.f;
                sRes[bb * 3 + 1] = (C >= 2.f) ? hs / fmaxf(C * (C - 1.f), 1.f) : 0.f;
                sRes[bb * 3 + 2] = (C >= 1.f) ? vr / Cs : 0.f;
            }
        }
        __syncthreads();

        if (tid == 0) {
            float mi = 0.f, me = 0.f, mr = 0.f;
#pragma unroll
            for (int q = 0; q < B_; q++) {
                mi += sRes[q * 3 + 0]; me += sRes[q * 3 + 1]; mr += sRes[q * 3 + 2];
            }
            mi *= 0.25f; me *= 0.25f; mr *= 0.25f;
            float bce = g_sBce / (float)((long)B_ * N_);
            out[0] = 1.0f * mi + 1.0f * me + 0.001f + mr + bce;
        }

        // reset counters for the next (graph-replayed) launch. Safe: done==69
        // transitively implies every wait in the grid has already passed.
        for (int i = tid; i < B_ * CHA_MAX; i += T_) g_rgn[i] = 0;
        for (int i = tid; i < 64; i += T_) g_beC[i] = 0;
        if (tid < B_) g_bC[tid] = 0;
        if (tid == 0) { g_p1C = 0; g_doneC = 0; }
    }
}

// ---------------------------------------------------------------------------
extern "C" void kernel_launch(void* const* d_in, const int* in_sizes, int n_in,
                              void* d_out, int out_size)
{
    (void)in_sizes; (void)n_in; (void)out_size;
    const float* emb   = (const float*)d_in[0];  // [4,16,96^3] f32
    const float* masks = (const float*)d_in[1];  // [4,1,96^3]  f32 logits
    const int*   lbl   = (const int*)d_in[2];    // [4,1,96^3]  int32 labels
    const float* tmask = (const float*)d_in[3];  // [4,1,96^3]  f32 0/1
    float* out = (float*)d_out;

    // Persistent dataflow grid MUST be fully resident.
    cudaFuncSetAttribute(k_all<1152>,
                         cudaFuncAttributePreferredSharedMemoryCarveout,
                         cudaSharedmemCarveoutMaxShared);
    cudaFuncSetAttribute(k_all<768>,
                         cudaFuncAttributePreferredSharedMemoryCarveout,
                         cudaSharedmemCarveoutMaxShared);
    int dev = 0;
    cudaGetDevice(&dev);
    int sms = 0;
    cudaDeviceGetAttribute(&sms, cudaDevAttrMultiProcessorCount, dev);
    int nb = 0;
    cudaOccupancyMaxActiveBlocksPerMultiprocessor(&nb, k_all<1152>, T_, 0);

    if ((long)nb * sms >= 1152)
        k_all<1152><<<1152, T_>>>(emb, masks, lbl, tmask, out);
    else
        k_all<768><<<768, T_>>>(emb, masks, lbl, tmask, out);
}